// round 4
// baseline (speedup 1.0000x reference)
#include <cuda_runtime.h>
#include <cstdint>

// ---------------------------------------------------------------------------
// C2QAttention: out[b,c,d] = sum_q softmax(sim[b,c,:])[q] * qenc[b,q,d]
// B=8, Tc=2048, Tq=1024, D=1024, fp32.
//
// Toolchain constraint (round-1 finding): PTX target is compute_103 (no 'a'),
// so tcgen05/TMEM are unavailable. Use mma.sync.m16n8k8 tf32 + ldmatrix
// (both base-target instructions).
//
// 3 kernels:
//   1) row softmax of sim -> P fp32 (tf32-rounded) scratch   [B,Tc,Tq]
//   2) transpose qenc -> Qt fp32 (tf32-rounded) scratch      [B,D,Tq]
//   3) batched GEMM out = P @ Qt^T, CTA tile 128x256, K-chunk 32,
//      2-stage cp.async pipeline, ldmatrix fragment loads.
// ---------------------------------------------------------------------------

#define BB 8
#define TC 2048
#define TQ 1024
#define DD 1024

__device__ float g_P [(size_t)BB * TC * TQ];   // 64 MB
__device__ float g_Qt[(size_t)BB * DD * TQ];   // 32 MB

// ---------------------------------------------------------------------------
// helpers
// ---------------------------------------------------------------------------
__device__ __forceinline__ uint32_t smem_u32(const void* p) {
    uint32_t a;
    asm("{ .reg .u64 t; cvta.to.shared.u64 t, %1; cvt.u32.u64 %0, t; }"
        : "=r"(a) : "l"(p));
    return a;
}

__device__ __forceinline__ float f2tf32(float f) {
    uint32_t u;
    asm("cvt.rna.tf32.f32 %0, %1;" : "=r"(u) : "f"(f));
    return __uint_as_float(u);
}

#define CP_ASYNC16(dst, src) \
    asm volatile("cp.async.cg.shared.global [%0], [%1], 16;" \
                 :: "r"(dst), "l"(src) : "memory")
#define CP_COMMIT() asm volatile("cp.async.commit_group;" ::: "memory")
#define CP_WAIT1()  asm volatile("cp.async.wait_group 1;" ::: "memory")
#define CP_WAIT0()  asm volatile("cp.async.wait_group 0;" ::: "memory")

__device__ __forceinline__ void ldmx4(uint32_t* r, uint32_t addr) {
    asm volatile("ldmatrix.sync.aligned.m8n8.x4.shared.b16 {%0,%1,%2,%3}, [%4];"
                 : "=r"(r[0]), "=r"(r[1]), "=r"(r[2]), "=r"(r[3])
                 : "r"(addr));
}

__device__ __forceinline__ void mma_tf32(float* d, const uint32_t* a,
                                         const uint32_t* b) {
    asm volatile(
        "mma.sync.aligned.m16n8k8.row.col.f32.tf32.tf32.f32 "
        "{%0,%1,%2,%3}, {%4,%5,%6,%7}, {%8,%9}, {%0,%1,%2,%3};"
        : "+f"(d[0]), "+f"(d[1]), "+f"(d[2]), "+f"(d[3])
        : "r"(a[0]), "r"(a[1]), "r"(a[2]), "r"(a[3]), "r"(b[0]), "r"(b[1]));
}

// ---------------------------------------------------------------------------
// Kernel 1: softmax over last axis, output tf32-rounded fp32.
// One block per row (Tq=1024), 256 threads x float4.
// ---------------------------------------------------------------------------
__global__ __launch_bounds__(256) void softmax_kernel(const float* __restrict__ sim) {
    const size_t row = blockIdx.x;
    const int t = threadIdx.x;
    const float4 v = reinterpret_cast<const float4*>(sim + row * TQ)[t];

    __shared__ float redm[8];
    __shared__ float reds[8];
    const int w = t >> 5, l = t & 31;

    float m = fmaxf(fmaxf(v.x, v.y), fmaxf(v.z, v.w));
    #pragma unroll
    for (int o = 16; o > 0; o >>= 1) m = fmaxf(m, __shfl_xor_sync(0xFFFFFFFFu, m, o));
    if (l == 0) redm[w] = m;
    __syncthreads();
    float rm = redm[0];
    #pragma unroll
    for (int i = 1; i < 8; ++i) rm = fmaxf(rm, redm[i]);

    const float e0 = __expf(v.x - rm);
    const float e1 = __expf(v.y - rm);
    const float e2 = __expf(v.z - rm);
    const float e3 = __expf(v.w - rm);
    float s = (e0 + e1) + (e2 + e3);
    #pragma unroll
    for (int o = 16; o > 0; o >>= 1) s += __shfl_xor_sync(0xFFFFFFFFu, s, o);
    if (l == 0) reds[w] = s;
    __syncthreads();
    float rs = reds[0];
    #pragma unroll
    for (int i = 1; i < 8; ++i) rs += reds[i];
    const float inv = 1.0f / rs;

    float4 o4;
    o4.x = f2tf32(e0 * inv);
    o4.y = f2tf32(e1 * inv);
    o4.z = f2tf32(e2 * inv);
    o4.w = f2tf32(e3 * inv);
    reinterpret_cast<float4*>(&g_P[row * TQ])[t] = o4;
}

// ---------------------------------------------------------------------------
// Kernel 2: transpose qenc [b,Tq,D] -> Qt [b,D,Tq], tf32-rounded.
// ---------------------------------------------------------------------------
__global__ __launch_bounds__(256) void transpose_kernel(const float* __restrict__ q) {
    __shared__ float tile[32][33];
    const int b = blockIdx.z;
    const int tq0 = blockIdx.x * 32;
    const int d0 = blockIdx.y * 32;
    const int tx = threadIdx.x, ty = threadIdx.y;

    const float* src = q + ((size_t)b * TQ + tq0) * DD + d0;
    #pragma unroll
    for (int i = 0; i < 4; ++i)
        tile[ty + 8 * i][tx] = src[(size_t)(ty + 8 * i) * DD + tx];
    __syncthreads();

    const size_t obase = ((size_t)b * DD + d0) * TQ + tq0;
    #pragma unroll
    for (int i = 0; i < 4; ++i)
        g_Qt[obase + (size_t)(ty + 8 * i) * TQ + tx] = f2tf32(tile[tx][ty + 8 * i]);
}

// ---------------------------------------------------------------------------
// Kernel 3: batched GEMM out[b] = P[b] (MxK) @ Qt[b]^T (KxN).
// CTA tile 128(M) x 256(N), 8 warps, warp tile 64x64, K-chunk 32.
// SMEM layout: 16B chunks, physical chunk = (row*8) | (kq ^ (row&7))
// -> conflict-free ldmatrix and conflict-free cp.async staging.
// ---------------------------------------------------------------------------
static constexpr int KC = 32;
static constexpr int NCH = TQ / KC;            // 32
static constexpr int BM = 128, BN = 256;
static constexpr int A_BYTES = BM * KC * 4;    // 16 KB
static constexpr int B_BYTES = BN * KC * 4;    // 32 KB
static constexpr int STAGE_B = A_BYTES + B_BYTES;      // 48 KB
static constexpr int SMEM_TOTAL = 2 * STAGE_B;         // 96 KB

__device__ __forceinline__ void stage_tiles(uint32_t sA, uint32_t sB,
                                            const float* __restrict__ gA,
                                            const float* __restrict__ gB,
                                            int tid) {
    // A: 128 rows x 8 chunks of 16B
    #pragma unroll
    for (int it = 0; it < 4; ++it) {
        const int v = (it << 8) + tid;
        const int m = v >> 3, kq = v & 7;
        const uint32_t dst = sA + ((uint32_t)((m << 3) | (kq ^ (m & 7))) << 4);
        CP_ASYNC16(dst, gA + (size_t)m * TQ + (kq << 2));
    }
    // B: 256 rows x 8 chunks of 16B
    #pragma unroll
    for (int it = 0; it < 8; ++it) {
        const int v = (it << 8) + tid;
        const int n = v >> 3, kq = v & 7;
        const uint32_t dst = sB + ((uint32_t)((n << 3) | (kq ^ (n & 7))) << 4);
        CP_ASYNC16(dst, gB + (size_t)n * TQ + (kq << 2));
    }
}

__global__ __launch_bounds__(256, 1) void gemm_tf32_kernel(float* __restrict__ out) {
    extern __shared__ __align__(128) char smem[];
    const uint32_t sb = smem_u32(smem);
    const int tid = threadIdx.x;
    const int lane = tid & 31;
    const int wid = tid >> 5;
    const int wm = (wid & 1) << 6;    // warp M offset: 0 or 64
    const int wn = (wid >> 1) << 6;   // warp N offset: 0,64,128,192

    const int b = blockIdx.z;
    const int m0 = blockIdx.y * BM;
    const int n0 = blockIdx.x * BN;

    const float* pA = g_P  + ((size_t)b * TC + m0) * TQ;
    const float* pB = g_Qt + ((size_t)b * DD + n0) * TQ;

    float acc[4][8][4];
    #pragma unroll
    for (int i = 0; i < 4; ++i)
        #pragma unroll
        for (int j = 0; j < 8; ++j)
            #pragma unroll
            for (int k = 0; k < 4; ++k) acc[i][j][k] = 0.0f;

    // ldmatrix per-thread row roles
    const int t7 = lane & 7;
    const int qd = lane >> 3;                    // matrix index 0..3
    const int a_mloc = t7 + ((qd & 1) << 3);     // A: row-in-m16 tile
    const int a_kh   = qd >> 1;                  // A: k-half (0/1)
    const int b_nloc = t7 + ((qd >> 1) << 3);    // B: row-in-n16 pair
    const int b_kh   = qd & 1;                   // B: k-half

    // prefetch chunk 0
    stage_tiles(sb, sb + A_BYTES, pA, pB, tid);
    CP_COMMIT();

    for (int c = 0; c < NCH; ++c) {
        if (c + 1 < NCH) {
            const uint32_t st = sb + (uint32_t)((c + 1) & 1) * STAGE_B;
            stage_tiles(st, st + A_BYTES, pA + (c + 1) * KC, pB + (c + 1) * KC, tid);
            CP_COMMIT();
            CP_WAIT1();
        } else {
            CP_WAIT0();
        }
        __syncthreads();

        const uint32_t sA = sb + (uint32_t)(c & 1) * STAGE_B;
        const uint32_t sB = sA + A_BYTES;

        #pragma unroll
        for (int s = 0; s < 4; ++s) {
            uint32_t afr[4][4];
            #pragma unroll
            for (int i = 0; i < 4; ++i) {
                const int m = wm + i * 16 + a_mloc;
                const int kq = 2 * s + a_kh;
                const uint32_t addr = sA + ((uint32_t)((m << 3) | (kq ^ (m & 7))) << 4);
                ldmx4(afr[i], addr);
            }
            uint32_t bfr[8][2];
            #pragma unroll
            for (int jj = 0; jj < 4; ++jj) {
                const int n = wn + jj * 16 + b_nloc;
                const int kq = 2 * s + b_kh;
                const uint32_t addr = sB + ((uint32_t)((n << 3) | (kq ^ (n & 7))) << 4);
                uint32_t r[4];
                ldmx4(r, addr);
                bfr[2 * jj][0] = r[0];
                bfr[2 * jj][1] = r[1];
                bfr[2 * jj + 1][0] = r[2];
                bfr[2 * jj + 1][1] = r[3];
            }
            #pragma unroll
            for (int i = 0; i < 4; ++i)
                #pragma unroll
                for (int j = 0; j < 8; ++j)
                    mma_tf32(acc[i][j], afr[i], bfr[j]);
        }
        __syncthreads();
    }

    // epilogue: c0,c1 at (row, 2*(lane%4)), c2,c3 at (row+8, same cols)
    const int r0 = lane >> 2;
    const int c0 = (lane & 3) << 1;
    float* ob = out + ((size_t)b * TC + m0 + wm + r0) * DD + (n0 + wn + c0);
    #pragma unroll
    for (int i = 0; i < 4; ++i) {
        #pragma unroll
        for (int j = 0; j < 8; ++j) {
            float2 v0 = make_float2(acc[i][j][0], acc[i][j][1]);
            float2 v1 = make_float2(acc[i][j][2], acc[i][j][3]);
            float* p = ob + (size_t)(i * 16) * DD + j * 8;
            *reinterpret_cast<float2*>(p) = v0;
            *reinterpret_cast<float2*>(p + (size_t)8 * DD) = v1;
        }
    }
}

// ---------------------------------------------------------------------------
// Launch
// ---------------------------------------------------------------------------
extern "C" void kernel_launch(void* const* d_in, const int* in_sizes, int n_in,
                              void* d_out, int out_size) {
    (void)in_sizes; (void)n_in; (void)out_size;
    const float* sim = (const float*)d_in[0];   // [8, 2048, 1024]
    const float* q   = (const float*)d_in[1];   // [8, 1024, 1024]
    float* out = (float*)d_out;                 // [8, 2048, 1024]

    softmax_kernel<<<BB * TC, 256>>>(sim);
    transpose_kernel<<<dim3(TQ / 32, DD / 32, BB), dim3(32, 8)>>>(q);

    cudaFuncSetAttribute(gemm_tf32_kernel,
                         cudaFuncAttributeMaxDynamicSharedMemorySize, SMEM_TOTAL);
    gemm_tf32_kernel<<<dim3(DD / BN, TC / BM, BB), 256, SMEM_TOTAL>>>(out);
}

// round 5
// speedup vs baseline: 1.0018x; 1.0018x over previous
#include <cuda_runtime.h>
#include <cstdint>

// ---------------------------------------------------------------------------
// C2QAttention: out[b,c,d] = sum_q softmax(sim[b,c,:])[q] * qenc[b,q,d]
// B=8, Tc=2048, Tq=1024, D=1024, fp32.
//
// Toolchain constraint (round-1 finding): PTX target is compute_103 (no 'a'),
// so tcgen05/TMEM are unavailable. Use mma.sync.m16n8k8 tf32 + ldmatrix
// (both base-target instructions).
//
// 3 kernels:
//   1) row softmax of sim -> P fp32 (tf32-rounded) scratch   [B,Tc,Tq]
//   2) transpose qenc -> Qt fp32 (tf32-rounded) scratch      [B,D,Tq]
//   3) batched GEMM out = P @ Qt^T, CTA tile 128x256, K-chunk 32,
//      2-stage cp.async pipeline, ldmatrix fragment loads.
// ---------------------------------------------------------------------------

#define BB 8
#define TC 2048
#define TQ 1024
#define DD 1024

__device__ float g_P [(size_t)BB * TC * TQ];   // 64 MB
__device__ float g_Qt[(size_t)BB * DD * TQ];   // 32 MB

// ---------------------------------------------------------------------------
// helpers
// ---------------------------------------------------------------------------
__device__ __forceinline__ uint32_t smem_u32(const void* p) {
    uint32_t a;
    asm("{ .reg .u64 t; cvta.to.shared.u64 t, %1; cvt.u32.u64 %0, t; }"
        : "=r"(a) : "l"(p));
    return a;
}

__device__ __forceinline__ float f2tf32(float f) {
    uint32_t u;
    asm("cvt.rna.tf32.f32 %0, %1;" : "=r"(u) : "f"(f));
    return __uint_as_float(u);
}

#define CP_ASYNC16(dst, src) \
    asm volatile("cp.async.cg.shared.global [%0], [%1], 16;" \
                 :: "r"(dst), "l"(src) : "memory")
#define CP_COMMIT() asm volatile("cp.async.commit_group;" ::: "memory")
#define CP_WAIT1()  asm volatile("cp.async.wait_group 1;" ::: "memory")
#define CP_WAIT0()  asm volatile("cp.async.wait_group 0;" ::: "memory")

__device__ __forceinline__ void ldmx4(uint32_t* r, uint32_t addr) {
    asm volatile("ldmatrix.sync.aligned.m8n8.x4.shared.b16 {%0,%1,%2,%3}, [%4];"
                 : "=r"(r[0]), "=r"(r[1]), "=r"(r[2]), "=r"(r[3])
                 : "r"(addr));
}

__device__ __forceinline__ void mma_tf32(float* d, const uint32_t* a,
                                         const uint32_t* b) {
    asm volatile(
        "mma.sync.aligned.m16n8k8.row.col.f32.tf32.tf32.f32 "
        "{%0,%1,%2,%3}, {%4,%5,%6,%7}, {%8,%9}, {%0,%1,%2,%3};"
        : "+f"(d[0]), "+f"(d[1]), "+f"(d[2]), "+f"(d[3])
        : "r"(a[0]), "r"(a[1]), "r"(a[2]), "r"(a[3]), "r"(b[0]), "r"(b[1]));
}

// ---------------------------------------------------------------------------
// Kernel 1: softmax over last axis, output tf32-rounded fp32.
// One block per row (Tq=1024), 256 threads x float4.
// ---------------------------------------------------------------------------
__global__ __launch_bounds__(256) void softmax_kernel(const float* __restrict__ sim) {
    const size_t row = blockIdx.x;
    const int t = threadIdx.x;
    const float4 v = reinterpret_cast<const float4*>(sim + row * TQ)[t];

    __shared__ float redm[8];
    __shared__ float reds[8];
    const int w = t >> 5, l = t & 31;

    float m = fmaxf(fmaxf(v.x, v.y), fmaxf(v.z, v.w));
    #pragma unroll
    for (int o = 16; o > 0; o >>= 1) m = fmaxf(m, __shfl_xor_sync(0xFFFFFFFFu, m, o));
    if (l == 0) redm[w] = m;
    __syncthreads();
    float rm = redm[0];
    #pragma unroll
    for (int i = 1; i < 8; ++i) rm = fmaxf(rm, redm[i]);

    const float e0 = __expf(v.x - rm);
    const float e1 = __expf(v.y - rm);
    const float e2 = __expf(v.z - rm);
    const float e3 = __expf(v.w - rm);
    float s = (e0 + e1) + (e2 + e3);
    #pragma unroll
    for (int o = 16; o > 0; o >>= 1) s += __shfl_xor_sync(0xFFFFFFFFu, s, o);
    if (l == 0) reds[w] = s;
    __syncthreads();
    float rs = reds[0];
    #pragma unroll
    for (int i = 1; i < 8; ++i) rs += reds[i];
    const float inv = 1.0f / rs;

    float4 o4;
    o4.x = f2tf32(e0 * inv);
    o4.y = f2tf32(e1 * inv);
    o4.z = f2tf32(e2 * inv);
    o4.w = f2tf32(e3 * inv);
    reinterpret_cast<float4*>(&g_P[row * TQ])[t] = o4;
}

// ---------------------------------------------------------------------------
// Kernel 2: transpose qenc [b,Tq,D] -> Qt [b,D,Tq], tf32-rounded.
// ---------------------------------------------------------------------------
__global__ __launch_bounds__(256) void transpose_kernel(const float* __restrict__ q) {
    __shared__ float tile[32][33];
    const int b = blockIdx.z;
    const int tq0 = blockIdx.x * 32;
    const int d0 = blockIdx.y * 32;
    const int tx = threadIdx.x, ty = threadIdx.y;

    const float* src = q + ((size_t)b * TQ + tq0) * DD + d0;
    #pragma unroll
    for (int i = 0; i < 4; ++i)
        tile[ty + 8 * i][tx] = src[(size_t)(ty + 8 * i) * DD + tx];
    __syncthreads();

    const size_t obase = ((size_t)b * DD + d0) * TQ + tq0;
    #pragma unroll
    for (int i = 0; i < 4; ++i)
        g_Qt[obase + (size_t)(ty + 8 * i) * TQ + tx] = f2tf32(tile[tx][ty + 8 * i]);
}

// ---------------------------------------------------------------------------
// Kernel 3: batched GEMM out[b] = P[b] (MxK) @ Qt[b]^T (KxN).
// CTA tile 128(M) x 256(N), 8 warps, warp tile 64x64, K-chunk 32.
// SMEM layout: 16B chunks, physical chunk = (row*8) | (kq ^ (row&7))
// -> conflict-free ldmatrix and conflict-free cp.async staging.
// ---------------------------------------------------------------------------
static constexpr int KC = 32;
static constexpr int NCH = TQ / KC;            // 32
static constexpr int BM = 128, BN = 256;
static constexpr int A_BYTES = BM * KC * 4;    // 16 KB
static constexpr int B_BYTES = BN * KC * 4;    // 32 KB
static constexpr int STAGE_B = A_BYTES + B_BYTES;      // 48 KB
static constexpr int SMEM_TOTAL = 2 * STAGE_B;         // 96 KB

__device__ __forceinline__ void stage_tiles(uint32_t sA, uint32_t sB,
                                            const float* __restrict__ gA,
                                            const float* __restrict__ gB,
                                            int tid) {
    // A: 128 rows x 8 chunks of 16B
    #pragma unroll
    for (int it = 0; it < 4; ++it) {
        const int v = (it << 8) + tid;
        const int m = v >> 3, kq = v & 7;
        const uint32_t dst = sA + ((uint32_t)((m << 3) | (kq ^ (m & 7))) << 4);
        CP_ASYNC16(dst, gA + (size_t)m * TQ + (kq << 2));
    }
    // B: 256 rows x 8 chunks of 16B
    #pragma unroll
    for (int it = 0; it < 8; ++it) {
        const int v = (it << 8) + tid;
        const int n = v >> 3, kq = v & 7;
        const uint32_t dst = sB + ((uint32_t)((n << 3) | (kq ^ (n & 7))) << 4);
        CP_ASYNC16(dst, gB + (size_t)n * TQ + (kq << 2));
    }
}

__global__ __launch_bounds__(256, 1) void gemm_tf32_kernel(float* __restrict__ out) {
    extern __shared__ __align__(128) char smem[];
    const uint32_t sb = smem_u32(smem);
    const int tid = threadIdx.x;
    const int lane = tid & 31;
    const int wid = tid >> 5;
    const int wm = (wid & 1) << 6;    // warp M offset: 0 or 64
    const int wn = (wid >> 1) << 6;   // warp N offset: 0,64,128,192

    const int b = blockIdx.z;
    const int m0 = blockIdx.y * BM;
    const int n0 = blockIdx.x * BN;

    const float* pA = g_P  + ((size_t)b * TC + m0) * TQ;
    const float* pB = g_Qt + ((size_t)b * DD + n0) * TQ;

    float acc[4][8][4];
    #pragma unroll
    for (int i = 0; i < 4; ++i)
        #pragma unroll
        for (int j = 0; j < 8; ++j)
            #pragma unroll
            for (int k = 0; k < 4; ++k) acc[i][j][k] = 0.0f;

    // ldmatrix per-thread row roles
    const int t7 = lane & 7;
    const int qd = lane >> 3;                    // matrix index 0..3
    const int a_mloc = t7 + ((qd & 1) << 3);     // A: row-in-m16 tile
    const int a_kh   = qd >> 1;                  // A: k-half (0/1)
    const int b_nloc = t7 + ((qd >> 1) << 3);    // B: row-in-n16 pair
    const int b_kh   = qd & 1;                   // B: k-half

    // prefetch chunk 0
    stage_tiles(sb, sb + A_BYTES, pA, pB, tid);
    CP_COMMIT();

    for (int c = 0; c < NCH; ++c) {
        if (c + 1 < NCH) {
            const uint32_t st = sb + (uint32_t)((c + 1) & 1) * STAGE_B;
            stage_tiles(st, st + A_BYTES, pA + (c + 1) * KC, pB + (c + 1) * KC, tid);
            CP_COMMIT();
            CP_WAIT1();
        } else {
            CP_WAIT0();
        }
        __syncthreads();

        const uint32_t sA = sb + (uint32_t)(c & 1) * STAGE_B;
        const uint32_t sB = sA + A_BYTES;

        #pragma unroll
        for (int s = 0; s < 4; ++s) {
            uint32_t afr[4][4];
            #pragma unroll
            for (int i = 0; i < 4; ++i) {
                const int m = wm + i * 16 + a_mloc;
                const int kq = 2 * s + a_kh;
                const uint32_t addr = sA + ((uint32_t)((m << 3) | (kq ^ (m & 7))) << 4);
                ldmx4(afr[i], addr);
            }
            uint32_t bfr[8][2];
            #pragma unroll
            for (int jj = 0; jj < 4; ++jj) {
                const int n = wn + jj * 16 + b_nloc;
                const int kq = 2 * s + b_kh;
                const uint32_t addr = sB + ((uint32_t)((n << 3) | (kq ^ (n & 7))) << 4);
                uint32_t r[4];
                ldmx4(r, addr);
                bfr[2 * jj][0] = r[0];
                bfr[2 * jj][1] = r[1];
                bfr[2 * jj + 1][0] = r[2];
                bfr[2 * jj + 1][1] = r[3];
            }
            #pragma unroll
            for (int i = 0; i < 4; ++i)
                #pragma unroll
                for (int j = 0; j < 8; ++j)
                    mma_tf32(acc[i][j], afr[i], bfr[j]);
        }
        __syncthreads();
    }

    // epilogue: c0,c1 at (row, 2*(lane%4)), c2,c3 at (row+8, same cols)
    const int r0 = lane >> 2;
    const int c0 = (lane & 3) << 1;
    float* ob = out + ((size_t)b * TC + m0 + wm + r0) * DD + (n0 + wn + c0);
    #pragma unroll
    for (int i = 0; i < 4; ++i) {
        #pragma unroll
        for (int j = 0; j < 8; ++j) {
            float2 v0 = make_float2(acc[i][j][0], acc[i][j][1]);
            float2 v1 = make_float2(acc[i][j][2], acc[i][j][3]);
            float* p = ob + (size_t)(i * 16) * DD + j * 8;
            *reinterpret_cast<float2*>(p) = v0;
            *reinterpret_cast<float2*>(p + (size_t)8 * DD) = v1;
        }
    }
}

// ---------------------------------------------------------------------------
// Launch
// ---------------------------------------------------------------------------
extern "C" void kernel_launch(void* const* d_in, const int* in_sizes, int n_in,
                              void* d_out, int out_size) {
    (void)in_sizes; (void)n_in; (void)out_size;
    const float* sim = (const float*)d_in[0];   // [8, 2048, 1024]
    const float* q   = (const float*)d_in[1];   // [8, 1024, 1024]
    float* out = (float*)d_out;                 // [8, 2048, 1024]

    softmax_kernel<<<BB * TC, 256>>>(sim);
    transpose_kernel<<<dim3(TQ / 32, DD / 32, BB), dim3(32, 8)>>>(q);

    cudaFuncSetAttribute(gemm_tf32_kernel,
                         cudaFuncAttributeMaxDynamicSharedMemorySize, SMEM_TOTAL);
    gemm_tf32_kernel<<<dim3(DD / BN, TC / BM, BB), 256, SMEM_TOTAL>>>(out);
}

// round 6
// speedup vs baseline: 1.5549x; 1.5522x over previous
#include <cuda_runtime.h>
#include <cuda_fp16.h>
#include <cstdint>

// ---------------------------------------------------------------------------
// C2QAttention: out[b,c,d] = sum_q softmax(sim[b,c,:])[q] * qenc[b,q,d]
// B=8, Tc=2048, Tq=1024, D=1024, fp32.
//
// Round 5 finding: legacy HMMA tf32 path is ~3x slower than modeled; fp16
// m16n8k16 has the SAME 10-bit mantissa as tf32 (rel_err unchanged ~3e-4)
// but 2x MAC/instr and half the operand bytes. Switch scratch + MMA to fp16,
// deepen cp.async pipeline to 4 stages.
// ---------------------------------------------------------------------------

#define BB 8
#define TC 2048
#define TQ 1024
#define DD 1024

__device__ __align__(256) __half g_P [(size_t)BB * TC * TQ];   // 32 MB
__device__ __align__(256) __half g_Qt[(size_t)BB * DD * TQ];   // 16 MB

// ---------------------------------------------------------------------------
// helpers
// ---------------------------------------------------------------------------
__device__ __forceinline__ uint32_t smem_u32(const void* p) {
    uint32_t a;
    asm("{ .reg .u64 t; cvta.to.shared.u64 t, %1; cvt.u32.u64 %0, t; }"
        : "=r"(a) : "l"(p));
    return a;
}

#define CP_ASYNC16(dst, src) \
    asm volatile("cp.async.cg.shared.global [%0], [%1], 16;" \
                 :: "r"(dst), "l"(src) : "memory")
#define CP_COMMIT() asm volatile("cp.async.commit_group;" ::: "memory")
#define CP_WAIT2()  asm volatile("cp.async.wait_group 2;" ::: "memory")
#define CP_WAIT1()  asm volatile("cp.async.wait_group 1;" ::: "memory")
#define CP_WAIT0()  asm volatile("cp.async.wait_group 0;" ::: "memory")

__device__ __forceinline__ void ldmx4(uint32_t* r, uint32_t addr) {
    asm volatile("ldmatrix.sync.aligned.m8n8.x4.shared.b16 {%0,%1,%2,%3}, [%4];"
                 : "=r"(r[0]), "=r"(r[1]), "=r"(r[2]), "=r"(r[3])
                 : "r"(addr));
}

__device__ __forceinline__ void mma_f16(float* d, const uint32_t* a,
                                        const uint32_t* b) {
    asm volatile(
        "mma.sync.aligned.m16n8k16.row.col.f32.f16.f16.f32 "
        "{%0,%1,%2,%3}, {%4,%5,%6,%7}, {%8,%9}, {%0,%1,%2,%3};"
        : "+f"(d[0]), "+f"(d[1]), "+f"(d[2]), "+f"(d[3])
        : "r"(a[0]), "r"(a[1]), "r"(a[2]), "r"(a[3]), "r"(b[0]), "r"(b[1]));
}

// ---------------------------------------------------------------------------
// Kernel 1: softmax over last axis -> fp16.
// One block per row (Tq=1024), 256 threads x float4.
// ---------------------------------------------------------------------------
__global__ __launch_bounds__(256) void softmax_kernel(const float* __restrict__ sim) {
    const size_t row = blockIdx.x;
    const int t = threadIdx.x;
    const float4 v = reinterpret_cast<const float4*>(sim + row * TQ)[t];

    __shared__ float redm[8];
    __shared__ float reds[8];
    const int w = t >> 5, l = t & 31;

    float m = fmaxf(fmaxf(v.x, v.y), fmaxf(v.z, v.w));
    #pragma unroll
    for (int o = 16; o > 0; o >>= 1) m = fmaxf(m, __shfl_xor_sync(0xFFFFFFFFu, m, o));
    if (l == 0) redm[w] = m;
    __syncthreads();
    float rm = redm[0];
    #pragma unroll
    for (int i = 1; i < 8; ++i) rm = fmaxf(rm, redm[i]);

    const float e0 = __expf(v.x - rm);
    const float e1 = __expf(v.y - rm);
    const float e2 = __expf(v.z - rm);
    const float e3 = __expf(v.w - rm);
    float s = (e0 + e1) + (e2 + e3);
    #pragma unroll
    for (int o = 16; o > 0; o >>= 1) s += __shfl_xor_sync(0xFFFFFFFFu, s, o);
    if (l == 0) reds[w] = s;
    __syncthreads();
    float rs = reds[0];
    #pragma unroll
    for (int i = 1; i < 8; ++i) rs += reds[i];
    const float inv = 1.0f / rs;

    __half2 h01 = __floats2half2_rn(e0 * inv, e1 * inv);
    __half2 h23 = __floats2half2_rn(e2 * inv, e3 * inv);
    uint2 u;
    u.x = *reinterpret_cast<uint32_t*>(&h01);
    u.y = *reinterpret_cast<uint32_t*>(&h23);
    *reinterpret_cast<uint2*>(&g_P[row * TQ + (size_t)t * 4]) = u;
}

// ---------------------------------------------------------------------------
// Kernel 2: transpose qenc [b,Tq,D] -> Qt [b,D,Tq] fp16.
// ---------------------------------------------------------------------------
__global__ __launch_bounds__(256) void transpose_kernel(const float* __restrict__ q) {
    __shared__ float tile[32][33];
    const int b = blockIdx.z;
    const int tq0 = blockIdx.x * 32;
    const int d0 = blockIdx.y * 32;
    const int tx = threadIdx.x, ty = threadIdx.y;

    const float* src = q + ((size_t)b * TQ + tq0) * DD + d0;
    #pragma unroll
    for (int i = 0; i < 4; ++i)
        tile[ty + 8 * i][tx] = src[(size_t)(ty + 8 * i) * DD + tx];
    __syncthreads();

    const size_t obase = ((size_t)b * DD + d0) * TQ + tq0;
    #pragma unroll
    for (int i = 0; i < 4; ++i)
        g_Qt[obase + (size_t)(ty + 8 * i) * TQ + tx] = __float2half_rn(tile[tx][ty + 8 * i]);
}

// ---------------------------------------------------------------------------
// Kernel 3: batched GEMM out[b] = P[b] (MxK) @ Qt[b]^T (KxN), fp16 MMA.
// CTA tile 128(M) x 256(N), 8 warps, warp tile 64x64.
// K-chunk 64 halves (128B rows), 4-stage cp.async pipeline.
// SMEM: 16B chunks, phys chunk = (row*8) | (kq ^ (row&7)) -> conflict-free.
// ---------------------------------------------------------------------------
static constexpr int KC = 64;                  // halves per chunk
static constexpr int NCH = TQ / KC;            // 16
static constexpr int BM = 128, BN = 256;
static constexpr int A_BYTES = BM * KC * 2;    // 16 KB
static constexpr int B_BYTES = BN * KC * 2;    // 32 KB
static constexpr int STAGE_B = A_BYTES + B_BYTES;      // 48 KB
static constexpr int NSTAGE = 4;
static constexpr int SMEM_TOTAL = NSTAGE * STAGE_B;    // 192 KB

__device__ __forceinline__ void stage_tiles(uint32_t sA, uint32_t sB,
                                            const __half* __restrict__ gA,
                                            const __half* __restrict__ gB,
                                            int tid) {
    // A: 128 rows x 8 chunks of 16B (8 halves each)
    #pragma unroll
    for (int it = 0; it < 4; ++it) {
        const int v = (it << 8) + tid;
        const int m = v >> 3, kq = v & 7;
        const uint32_t dst = sA + ((uint32_t)((m << 3) | (kq ^ (m & 7))) << 4);
        CP_ASYNC16(dst, gA + (size_t)m * TQ + (kq << 3));
    }
    // B: 256 rows x 8 chunks
    #pragma unroll
    for (int it = 0; it < 8; ++it) {
        const int v = (it << 8) + tid;
        const int n = v >> 3, kq = v & 7;
        const uint32_t dst = sB + ((uint32_t)((n << 3) | (kq ^ (n & 7))) << 4);
        CP_ASYNC16(dst, gB + (size_t)n * TQ + (kq << 3));
    }
}

__global__ __launch_bounds__(256, 1) void gemm_f16_kernel(float* __restrict__ out) {
    extern __shared__ __align__(128) char smem[];
    const uint32_t sb = smem_u32(smem);
    const int tid = threadIdx.x;
    const int lane = tid & 31;
    const int wid = tid >> 5;
    const int wm = (wid & 1) << 6;    // warp M offset: 0 or 64
    const int wn = (wid >> 1) << 6;   // warp N offset: 0,64,128,192

    const int b = blockIdx.z;
    const int m0 = blockIdx.y * BM;
    const int n0 = blockIdx.x * BN;

    const __half* pA = g_P  + ((size_t)b * TC + m0) * TQ;
    const __half* pB = g_Qt + ((size_t)b * DD + n0) * TQ;

    float acc[4][8][4];
    #pragma unroll
    for (int i = 0; i < 4; ++i)
        #pragma unroll
        for (int j = 0; j < 8; ++j)
            #pragma unroll
            for (int k = 0; k < 4; ++k) acc[i][j][k] = 0.0f;

    // ldmatrix per-lane addressing roles (x4: lanes/8 -> matrix index)
    const int t7 = lane & 7;
    const int qd = lane >> 3;                 // matrix index 0..3
    const int rloc = t7 + ((qd & 1) << 3);    // row within 16-row group
    const int khf  = qd >> 1;                 // k-half (which 16B chunk of k16)

    // prologue: stage chunks 0,1,2
    #pragma unroll
    for (int c = 0; c < 3; ++c) {
        const uint32_t st = sb + (uint32_t)c * STAGE_B;
        stage_tiles(st, st + A_BYTES, pA + c * KC, pB + c * KC, tid);
        CP_COMMIT();
    }

    for (int c = 0; c < NCH; ++c) {
        if (c < NCH - 2)      CP_WAIT2();
        else if (c == NCH - 2) CP_WAIT1();
        else                   CP_WAIT0();
        __syncthreads();

        const uint32_t sA = sb + (uint32_t)(c & 3) * STAGE_B;
        const uint32_t sB = sA + A_BYTES;

        #pragma unroll
        for (int s = 0; s < 4; ++s) {       // k16 steps within 64-k chunk
            const int kq = 2 * s + khf;     // 16B chunk index in row
            uint32_t afr[4][4];
            #pragma unroll
            for (int i = 0; i < 4; ++i) {
                const int m = wm + i * 16 + rloc;
                const uint32_t addr = sA + ((uint32_t)((m << 3) | (kq ^ (m & 7))) << 4);
                ldmx4(afr[i], addr);
            }
            uint32_t bfr[8][2];
            #pragma unroll
            for (int jj = 0; jj < 4; ++jj) {
                const int n = wn + jj * 16 + rloc;
                const uint32_t addr = sB + ((uint32_t)((n << 3) | (kq ^ (n & 7))) << 4);
                uint32_t r[4];
                ldmx4(r, addr);
                bfr[2 * jj][0]     = r[0];  // n-lo: k0-7
                bfr[2 * jj][1]     = r[2];  // n-lo: k8-15
                bfr[2 * jj + 1][0] = r[1];  // n-hi: k0-7
                bfr[2 * jj + 1][1] = r[3];  // n-hi: k8-15
            }
            #pragma unroll
            for (int i = 0; i < 4; ++i)
                #pragma unroll
                for (int j = 0; j < 8; ++j)
                    mma_f16(acc[i][j], afr[i], bfr[j]);
        }
        __syncthreads();

        if (c + 3 < NCH) {
            const uint32_t st = sb + (uint32_t)((c + 3) & 3) * STAGE_B;
            stage_tiles(st, st + A_BYTES, pA + (c + 3) * KC, pB + (c + 3) * KC, tid);
            CP_COMMIT();
        }
    }

    // epilogue: c0,c1 at (row, 2*(lane%4)), c2,c3 at (row+8, same cols)
    const int r0 = lane >> 2;
    const int c0 = (lane & 3) << 1;
    float* ob = out + ((size_t)b * TC + m0 + wm + r0) * DD + (n0 + wn + c0);
    #pragma unroll
    for (int i = 0; i < 4; ++i) {
        #pragma unroll
        for (int j = 0; j < 8; ++j) {
            float2 v0 = make_float2(acc[i][j][0], acc[i][j][1]);
            float2 v1 = make_float2(acc[i][j][2], acc[i][j][3]);
            float* p = ob + (size_t)(i * 16) * DD + j * 8;
            *reinterpret_cast<float2*>(p) = v0;
            *reinterpret_cast<float2*>(p + (size_t)8 * DD) = v1;
        }
    }
}

// ---------------------------------------------------------------------------
// Launch
// ---------------------------------------------------------------------------
extern "C" void kernel_launch(void* const* d_in, const int* in_sizes, int n_in,
                              void* d_out, int out_size) {
    (void)in_sizes; (void)n_in; (void)out_size;
    const float* sim = (const float*)d_in[0];   // [8, 2048, 1024]
    const float* q   = (const float*)d_in[1];   // [8, 1024, 1024]
    float* out = (float*)d_out;                 // [8, 2048, 1024]

    softmax_kernel<<<BB * TC, 256>>>(sim);
    transpose_kernel<<<dim3(TQ / 32, DD / 32, BB), dim3(32, 8)>>>(q);

    cudaFuncSetAttribute(gemm_f16_kernel,
                         cudaFuncAttributeMaxDynamicSharedMemorySize, SMEM_TOTAL);
    gemm_f16_kernel<<<dim3(DD / BN, TC / BM, BB), 256, SMEM_TOTAL>>>(out);
}

// round 11
// speedup vs baseline: 1.6156x; 1.0390x over previous
#include <cuda_runtime.h>
#include <cuda_fp16.h>
#include <cstdint>

// ---------------------------------------------------------------------------
// C2QAttention: out[b,c,d] = sum_q softmax(sim[b,c,:])[q] * qenc[b,q,d]
// B=8, Tc=2048, Tq=1024, D=1024, fp32.
//
// fp16 m16n8k16 MMA (same 10-bit mantissa as tf32 -> rel_err ~3e-4).
// Round 7: warp-per-row softmax (no barriers); GEMM fragment double-buffer
// pipelining + early cp.async staging + 1 barrier/chunk.
// ---------------------------------------------------------------------------

#define BB 8
#define TC 2048
#define TQ 1024
#define DD 1024

__device__ __align__(256) __half g_P [(size_t)BB * TC * TQ];   // 32 MB
__device__ __align__(256) __half g_Qt[(size_t)BB * DD * TQ];   // 16 MB

// ---------------------------------------------------------------------------
// helpers
// ---------------------------------------------------------------------------
__device__ __forceinline__ uint32_t smem_u32(const void* p) {
    uint32_t a;
    asm("{ .reg .u64 t; cvta.to.shared.u64 t, %1; cvt.u32.u64 %0, t; }"
        : "=r"(a) : "l"(p));
    return a;
}

#define CP_ASYNC16(dst, src) \
    asm volatile("cp.async.cg.shared.global [%0], [%1], 16;" \
                 :: "r"(dst), "l"(src) : "memory")
#define CP_COMMIT() asm volatile("cp.async.commit_group;" ::: "memory")
#define CP_WAIT2()  asm volatile("cp.async.wait_group 2;" ::: "memory")
#define CP_WAIT1()  asm volatile("cp.async.wait_group 1;" ::: "memory")
#define CP_WAIT0()  asm volatile("cp.async.wait_group 0;" ::: "memory")

__device__ __forceinline__ void ldmx4(uint32_t* r, uint32_t addr) {
    asm volatile("ldmatrix.sync.aligned.m8n8.x4.shared.b16 {%0,%1,%2,%3}, [%4];"
                 : "=r"(r[0]), "=r"(r[1]), "=r"(r[2]), "=r"(r[3])
                 : "r"(addr));
}

__device__ __forceinline__ void mma_f16(float* d, const uint32_t* a,
                                        const uint32_t* b) {
    asm volatile(
        "mma.sync.aligned.m16n8k16.row.col.f32.f16.f16.f32 "
        "{%0,%1,%2,%3}, {%4,%5,%6,%7}, {%8,%9}, {%0,%1,%2,%3};"
        : "+f"(d[0]), "+f"(d[1]), "+f"(d[2]), "+f"(d[3])
        : "r"(a[0]), "r"(a[1]), "r"(a[2]), "r"(a[3]), "r"(b[0]), "r"(b[1]));
}

// ---------------------------------------------------------------------------
// Kernel 1: softmax, one WARP per row. 256 threads = 8 rows/block.
// Each lane: 8 x float4 (32 elements). Shuffle-only reductions.
// ---------------------------------------------------------------------------
__global__ __launch_bounds__(256) void softmax_kernel(const float* __restrict__ sim) {
    const size_t row = (size_t)blockIdx.x * 8 + (threadIdx.x >> 5);
    const int l = threadIdx.x & 31;
    const float4* src = reinterpret_cast<const float4*>(sim + row * TQ);

    float4 v[8];
    #pragma unroll
    for (int i = 0; i < 8; ++i) v[i] = src[l + 32 * i];

    float m = -1e30f;
    #pragma unroll
    for (int i = 0; i < 8; ++i)
        m = fmaxf(m, fmaxf(fmaxf(v[i].x, v[i].y), fmaxf(v[i].z, v[i].w)));
    #pragma unroll
    for (int o = 16; o > 0; o >>= 1) m = fmaxf(m, __shfl_xor_sync(0xFFFFFFFFu, m, o));

    float e[8][4];
    float s = 0.0f;
    #pragma unroll
    for (int i = 0; i < 8; ++i) {
        e[i][0] = __expf(v[i].x - m);
        e[i][1] = __expf(v[i].y - m);
        e[i][2] = __expf(v[i].z - m);
        e[i][3] = __expf(v[i].w - m);
        s += (e[i][0] + e[i][1]) + (e[i][2] + e[i][3]);
    }
    #pragma unroll
    for (int o = 16; o > 0; o >>= 1) s += __shfl_xor_sync(0xFFFFFFFFu, s, o);
    const float inv = 1.0f / s;

    __half* dst = g_P + row * TQ;
    #pragma unroll
    for (int i = 0; i < 8; ++i) {
        __half2 h01 = __floats2half2_rn(e[i][0] * inv, e[i][1] * inv);
        __half2 h23 = __floats2half2_rn(e[i][2] * inv, e[i][3] * inv);
        uint2 u;
        u.x = *reinterpret_cast<uint32_t*>(&h01);
        u.y = *reinterpret_cast<uint32_t*>(&h23);
        *reinterpret_cast<uint2*>(dst + (size_t)(l + 32 * i) * 4) = u;
    }
}

// ---------------------------------------------------------------------------
// Kernel 2: transpose qenc [b,Tq,D] -> Qt [b,D,Tq] fp16.
// ---------------------------------------------------------------------------
__global__ __launch_bounds__(256) void transpose_kernel(const float* __restrict__ q) {
    __shared__ float tile[32][33];
    const int b = blockIdx.z;
    const int tq0 = blockIdx.x * 32;
    const int d0 = blockIdx.y * 32;
    const int tx = threadIdx.x, ty = threadIdx.y;

    const float* src = q + ((size_t)b * TQ + tq0) * DD + d0;
    #pragma unroll
    for (int i = 0; i < 4; ++i)
        tile[ty + 8 * i][tx] = src[(size_t)(ty + 8 * i) * DD + tx];
    __syncthreads();

    const size_t obase = ((size_t)b * DD + d0) * TQ + tq0;
    #pragma unroll
    for (int i = 0; i < 4; ++i)
        g_Qt[obase + (size_t)(ty + 8 * i) * TQ + tx] = __float2half_rn(tile[tx][ty + 8 * i]);
}

// ---------------------------------------------------------------------------
// Kernel 3: batched GEMM out[b] = P[b] (MxK) @ Qt[b]^T (KxN), fp16 MMA.
// CTA tile 128(M) x 256(N), 8 warps, warp tile 64x64.
// K-chunk 64, 4-stage cp.async, fragment double-buffer pipelining.
// ---------------------------------------------------------------------------
static constexpr int KC = 64;
static constexpr int NCH = TQ / KC;            // 16
static constexpr int BM = 128, BN = 256;
static constexpr int A_BYTES = BM * KC * 2;    // 16 KB
static constexpr int B_BYTES = BN * KC * 2;    // 32 KB
static constexpr int STAGE_B = A_BYTES + B_BYTES;      // 48 KB
static constexpr int NSTAGE = 4;
static constexpr int SMEM_TOTAL = NSTAGE * STAGE_B;    // 192 KB

__device__ __forceinline__ void stage_tiles(uint32_t sA, uint32_t sB,
                                            const __half* __restrict__ gA,
                                            const __half* __restrict__ gB,
                                            int tid) {
    #pragma unroll
    for (int it = 0; it < 4; ++it) {
        const int v = (it << 8) + tid;
        const int m = v >> 3, kq = v & 7;
        const uint32_t dst = sA + ((uint32_t)((m << 3) | (kq ^ (m & 7))) << 4);
        CP_ASYNC16(dst, gA + (size_t)m * TQ + (kq << 3));
    }
    #pragma unroll
    for (int it = 0; it < 8; ++it) {
        const int v = (it << 8) + tid;
        const int n = v >> 3, kq = v & 7;
        const uint32_t dst = sB + ((uint32_t)((n << 3) | (kq ^ (n & 7))) << 4);
        CP_ASYNC16(dst, gB + (size_t)n * TQ + (kq << 3));
    }
}

struct Frag { uint32_t a[4][4]; uint32_t b[8][2]; };

__device__ __forceinline__ void load_frags(Frag& f, uint32_t sA, uint32_t sB,
                                           int wm, int wn, int rloc, int khf, int s) {
    const int kq = 2 * s + khf;
    #pragma unroll
    for (int i = 0; i < 4; ++i) {
        const int m = wm + i * 16 + rloc;
        ldmx4(f.a[i], sA + ((uint32_t)((m << 3) | (kq ^ (m & 7))) << 4));
    }
    #pragma unroll
    for (int jj = 0; jj < 4; ++jj) {
        const int n = wn + jj * 16 + rloc;
        uint32_t r[4];
        ldmx4(r, sB + ((uint32_t)((n << 3) | (kq ^ (n & 7))) << 4));
        f.b[2 * jj][0]     = r[0];
        f.b[2 * jj][1]     = r[2];
        f.b[2 * jj + 1][0] = r[1];
        f.b[2 * jj + 1][1] = r[3];
    }
}

__global__ __launch_bounds__(256, 1) void gemm_f16_kernel(float* __restrict__ out) {
    extern __shared__ __align__(128) char smem[];
    const uint32_t sb = smem_u32(smem);
    const int tid = threadIdx.x;
    const int lane = tid & 31;
    const int wid = tid >> 5;
    const int wm = (wid & 1) << 6;
    const int wn = (wid >> 1) << 6;

    const int b = blockIdx.z;
    const int m0 = blockIdx.y * BM;
    const int n0 = blockIdx.x * BN;

    const __half* pA = g_P  + ((size_t)b * TC + m0) * TQ;
    const __half* pB = g_Qt + ((size_t)b * DD + n0) * TQ;

    float acc[4][8][4];
    #pragma unroll
    for (int i = 0; i < 4; ++i)
        #pragma unroll
        for (int j = 0; j < 8; ++j)
            #pragma unroll
            for (int k = 0; k < 4; ++k) acc[i][j][k] = 0.0f;

    const int t7 = lane & 7;
    const int qd = lane >> 3;
    const int rloc = t7 + ((qd & 1) << 3);
    const int khf  = qd >> 1;

    // prologue: stage chunks 0,1,2
    #pragma unroll
    for (int c = 0; c < 3; ++c) {
        const uint32_t st = sb + (uint32_t)c * STAGE_B;
        stage_tiles(st, st + A_BYTES, pA + c * KC, pB + c * KC, tid);
        CP_COMMIT();
    }

    Frag fr[2];

    for (int c = 0; c < NCH; ++c) {
        if (c < NCH - 2)       CP_WAIT2();
        else if (c == NCH - 2) CP_WAIT1();
        else                   CP_WAIT0();
        __syncthreads();   // stage c ready; all warps done reading stage (c+3)&3

        // overlap next DMA with the whole chunk's compute
        if (c + 3 < NCH) {
            const uint32_t st = sb + (uint32_t)((c + 3) & 3) * STAGE_B;
            stage_tiles(st, st + A_BYTES, pA + (c + 3) * KC, pB + (c + 3) * KC, tid);
            CP_COMMIT();
        }

        const uint32_t sA = sb + (uint32_t)(c & 3) * STAGE_B;
        const uint32_t sB = sA + A_BYTES;

        load_frags(fr[0], sA, sB, wm, wn, rloc, khf, 0);
        #pragma unroll
        for (int s = 0; s < 4; ++s) {
            if (s < 3) load_frags(fr[(s + 1) & 1], sA, sB, wm, wn, rloc, khf, s + 1);
            Frag& f = fr[s & 1];
            #pragma unroll
            for (int i = 0; i < 4; ++i)
                #pragma unroll
                for (int j = 0; j < 8; ++j)
                    mma_f16(acc[i][j], f.a[i], f.b[j]);
        }
    }

    // epilogue
    const int r0 = lane >> 2;
    const int c0 = (lane & 3) << 1;
    float* ob = out + ((size_t)b * TC + m0 + wm + r0) * DD + (n0 + wn + c0);
    #pragma unroll
    for (int i = 0; i < 4; ++i) {
        #pragma unroll
        for (int j = 0; j < 8; ++j) {
            float2 v0 = make_float2(acc[i][j][0], acc[i][j][1]);
            float2 v1 = make_float2(acc[i][j][2], acc[i][j][3]);
            float* p = ob + (size_t)(i * 16) * DD + j * 8;
            *reinterpret_cast<float2*>(p) = v0;
            *reinterpret_cast<float2*>(p + (size_t)8 * DD) = v1;
        }
    }
}

// ---------------------------------------------------------------------------
// Launch
// ---------------------------------------------------------------------------
extern "C" void kernel_launch(void* const* d_in, const int* in_sizes, int n_in,
                              void* d_out, int out_size) {
    (void)in_sizes; (void)n_in; (void)out_size;
    const float* sim = (const float*)d_in[0];   // [8, 2048, 1024]
    const float* q   = (const float*)d_in[1];   // [8, 1024, 1024]
    float* out = (float*)d_out;                 // [8, 2048, 1024]

    softmax_kernel<<<BB * TC / 8, 256>>>(sim);
    transpose_kernel<<<dim3(TQ / 32, DD / 32, BB), dim3(32, 8)>>>(q);

    cudaFuncSetAttribute(gemm_f16_kernel,
                         cudaFuncAttributeMaxDynamicSharedMemorySize, SMEM_TOTAL);
    gemm_f16_kernel<<<dim3(DD / BN, TC / BM, BB), 256, SMEM_TOTAL>>>(out);
}

// round 12
// speedup vs baseline: 1.8345x; 1.1355x over previous
#include <cuda_runtime.h>
#include <cuda_fp16.h>
#include <cstdint>

// ---------------------------------------------------------------------------
// C2QAttention: out[b,c,d] = sum_q softmax(sim[b,c,:])[q] * qenc[b,q,d]
// B=8, Tc=2048, Tq=1024, D=1024, fp32.
//
// fp16 m16n8k16 MMA (same 10-bit mantissa as tf32 -> rel_err ~3e-4).
// Round 12: GEMM re-tiled to 128x128 / 128 threads / 3x32KB stages so that
// TWO CTAs co-reside per SM -> tensor-pipe bubbles (prologue, barriers,
// epilogue, ragged tail) are filled by the sibling CTA.
// ---------------------------------------------------------------------------

#define BB 8
#define TC 2048
#define TQ 1024
#define DD 1024

__device__ __align__(256) __half g_P [(size_t)BB * TC * TQ];   // 32 MB
__device__ __align__(256) __half g_Qt[(size_t)BB * DD * TQ];   // 16 MB

// ---------------------------------------------------------------------------
// helpers
// ---------------------------------------------------------------------------
__device__ __forceinline__ uint32_t smem_u32(const void* p) {
    uint32_t a;
    asm("{ .reg .u64 t; cvta.to.shared.u64 t, %1; cvt.u32.u64 %0, t; }"
        : "=r"(a) : "l"(p));
    return a;
}

#define CP_ASYNC16(dst, src) \
    asm volatile("cp.async.cg.shared.global [%0], [%1], 16;" \
                 :: "r"(dst), "l"(src) : "memory")
#define CP_COMMIT() asm volatile("cp.async.commit_group;" ::: "memory")
#define CP_WAIT1()  asm volatile("cp.async.wait_group 1;" ::: "memory")
#define CP_WAIT0()  asm volatile("cp.async.wait_group 0;" ::: "memory")

__device__ __forceinline__ void ldmx4(uint32_t* r, uint32_t addr) {
    asm volatile("ldmatrix.sync.aligned.m8n8.x4.shared.b16 {%0,%1,%2,%3}, [%4];"
                 : "=r"(r[0]), "=r"(r[1]), "=r"(r[2]), "=r"(r[3])
                 : "r"(addr));
}

__device__ __forceinline__ void mma_f16(float* d, const uint32_t* a,
                                        const uint32_t* b) {
    asm volatile(
        "mma.sync.aligned.m16n8k16.row.col.f32.f16.f16.f32 "
        "{%0,%1,%2,%3}, {%4,%5,%6,%7}, {%8,%9}, {%0,%1,%2,%3};"
        : "+f"(d[0]), "+f"(d[1]), "+f"(d[2]), "+f"(d[3])
        : "r"(a[0]), "r"(a[1]), "r"(a[2]), "r"(a[3]), "r"(b[0]), "r"(b[1]));
}

// ---------------------------------------------------------------------------
// Kernel 1: softmax, one WARP per row. 256 threads = 8 rows/block.
// ---------------------------------------------------------------------------
__global__ __launch_bounds__(256) void softmax_kernel(const float* __restrict__ sim) {
    const size_t row = (size_t)blockIdx.x * 8 + (threadIdx.x >> 5);
    const int l = threadIdx.x & 31;
    const float4* src = reinterpret_cast<const float4*>(sim + row * TQ);

    float4 v[8];
    #pragma unroll
    for (int i = 0; i < 8; ++i) v[i] = src[l + 32 * i];

    float m = -1e30f;
    #pragma unroll
    for (int i = 0; i < 8; ++i)
        m = fmaxf(m, fmaxf(fmaxf(v[i].x, v[i].y), fmaxf(v[i].z, v[i].w)));
    #pragma unroll
    for (int o = 16; o > 0; o >>= 1) m = fmaxf(m, __shfl_xor_sync(0xFFFFFFFFu, m, o));

    float e[8][4];
    float s = 0.0f;
    #pragma unroll
    for (int i = 0; i < 8; ++i) {
        e[i][0] = __expf(v[i].x - m);
        e[i][1] = __expf(v[i].y - m);
        e[i][2] = __expf(v[i].z - m);
        e[i][3] = __expf(v[i].w - m);
        s += (e[i][0] + e[i][1]) + (e[i][2] + e[i][3]);
    }
    #pragma unroll
    for (int o = 16; o > 0; o >>= 1) s += __shfl_xor_sync(0xFFFFFFFFu, s, o);
    const float inv = 1.0f / s;

    __half* dst = g_P + row * TQ;
    #pragma unroll
    for (int i = 0; i < 8; ++i) {
        __half2 h01 = __floats2half2_rn(e[i][0] * inv, e[i][1] * inv);
        __half2 h23 = __floats2half2_rn(e[i][2] * inv, e[i][3] * inv);
        uint2 u;
        u.x = *reinterpret_cast<uint32_t*>(&h01);
        u.y = *reinterpret_cast<uint32_t*>(&h23);
        *reinterpret_cast<uint2*>(dst + (size_t)(l + 32 * i) * 4) = u;
    }
}

// ---------------------------------------------------------------------------
// Kernel 2: transpose qenc [b,Tq,D] -> Qt [b,D,Tq] fp16.
// ---------------------------------------------------------------------------
__global__ __launch_bounds__(256) void transpose_kernel(const float* __restrict__ q) {
    __shared__ float tile[32][33];
    const int b = blockIdx.z;
    const int tq0 = blockIdx.x * 32;
    const int d0 = blockIdx.y * 32;
    const int tx = threadIdx.x, ty = threadIdx.y;

    const float* src = q + ((size_t)b * TQ + tq0) * DD + d0;
    #pragma unroll
    for (int i = 0; i < 4; ++i)
        tile[ty + 8 * i][tx] = src[(size_t)(ty + 8 * i) * DD + tx];
    __syncthreads();

    const size_t obase = ((size_t)b * DD + d0) * TQ + tq0;
    #pragma unroll
    for (int i = 0; i < 4; ++i)
        g_Qt[obase + (size_t)(ty + 8 * i) * TQ + tx] = __float2half_rn(tile[tx][ty + 8 * i]);
}

// ---------------------------------------------------------------------------
// Kernel 3: batched GEMM out[b] = P[b] (MxK) @ Qt[b]^T (KxN), fp16 MMA.
// CTA tile 128x128, 4 warps (warp tile 64x64), K-chunk 64,
// 3-stage cp.async pipeline (96 KB) -> 2 CTAs per SM.
// SMEM: 16B chunks, phys chunk = (row*8) | (kq ^ (row&7)) -> conflict-free.
// ---------------------------------------------------------------------------
static constexpr int KC = 64;
static constexpr int NCH = TQ / KC;            // 16
static constexpr int BM = 128, BN = 128;
static constexpr int A_BYTES = BM * KC * 2;    // 16 KB
static constexpr int B_BYTES = BN * KC * 2;    // 16 KB
static constexpr int STAGE_B = A_BYTES + B_BYTES;      // 32 KB
static constexpr int NSTAGE = 3;
static constexpr int SMEM_TOTAL = NSTAGE * STAGE_B;    // 96 KB
static constexpr int GTHREADS = 128;

__device__ __forceinline__ void stage_tiles(uint32_t sA, uint32_t sB,
                                            const __half* __restrict__ gA,
                                            const __half* __restrict__ gB,
                                            int tid) {
    // A: 128 rows x 8 chunks of 16B; 1024 chunks / 128 thr = 8 iters
    #pragma unroll
    for (int it = 0; it < 8; ++it) {
        const int v = (it << 7) + tid;
        const int m = v >> 3, kq = v & 7;
        const uint32_t dst = sA + ((uint32_t)((m << 3) | (kq ^ (m & 7))) << 4);
        CP_ASYNC16(dst, gA + (size_t)m * TQ + (kq << 3));
    }
    // B: 128 rows x 8 chunks
    #pragma unroll
    for (int it = 0; it < 8; ++it) {
        const int v = (it << 7) + tid;
        const int n = v >> 3, kq = v & 7;
        const uint32_t dst = sB + ((uint32_t)((n << 3) | (kq ^ (n & 7))) << 4);
        CP_ASYNC16(dst, gB + (size_t)n * TQ + (kq << 3));
    }
}

struct Frag { uint32_t a[4][4]; uint32_t b[8][2]; };

__device__ __forceinline__ void load_frags(Frag& f, uint32_t sA, uint32_t sB,
                                           int wm, int wn, int rloc, int khf, int s) {
    const int kq = 2 * s + khf;
    #pragma unroll
    for (int i = 0; i < 4; ++i) {
        const int m = wm + i * 16 + rloc;
        ldmx4(f.a[i], sA + ((uint32_t)((m << 3) | (kq ^ (m & 7))) << 4));
    }
    #pragma unroll
    for (int jj = 0; jj < 4; ++jj) {
        const int n = wn + jj * 16 + rloc;
        uint32_t r[4];
        ldmx4(r, sB + ((uint32_t)((n << 3) | (kq ^ (n & 7))) << 4));
        f.b[2 * jj][0]     = r[0];
        f.b[2 * jj][1]     = r[2];
        f.b[2 * jj + 1][0] = r[1];
        f.b[2 * jj + 1][1] = r[3];
    }
}

__global__ __launch_bounds__(GTHREADS, 2) void gemm_f16_kernel(float* __restrict__ out) {
    extern __shared__ __align__(128) char smem[];
    const uint32_t sb = smem_u32(smem);
    const int tid = threadIdx.x;
    const int lane = tid & 31;
    const int wid = tid >> 5;
    const int wm = (wid & 1) << 6;   // 0 or 64
    const int wn = (wid >> 1) << 6;  // 0 or 64

    const int b = blockIdx.z;
    const int m0 = blockIdx.y * BM;
    const int n0 = blockIdx.x * BN;

    const __half* pA = g_P  + ((size_t)b * TC + m0) * TQ;
    const __half* pB = g_Qt + ((size_t)b * DD + n0) * TQ;

    float acc[4][8][4];
    #pragma unroll
    for (int i = 0; i < 4; ++i)
        #pragma unroll
        for (int j = 0; j < 8; ++j)
            #pragma unroll
            for (int k = 0; k < 4; ++k) acc[i][j][k] = 0.0f;

    const int t7 = lane & 7;
    const int qd = lane >> 3;
    const int rloc = t7 + ((qd & 1) << 3);
    const int khf  = qd >> 1;

    // prologue: stage chunks 0,1
    #pragma unroll
    for (int c = 0; c < 2; ++c) {
        const uint32_t st = sb + (uint32_t)c * STAGE_B;
        stage_tiles(st, st + A_BYTES, pA + c * KC, pB + c * KC, tid);
        CP_COMMIT();
    }

    Frag fr[2];

    for (int c = 0; c < NCH; ++c) {
        if (c < NCH - 1) CP_WAIT1();
        else             CP_WAIT0();
        __syncthreads();   // stage c ready; all warps done reading stage c-1

        // overlap next DMA with this chunk's compute
        if (c + 2 < NCH) {
            const uint32_t st = sb + (uint32_t)((c + 2) % 3) * STAGE_B;
            stage_tiles(st, st + A_BYTES, pA + (c + 2) * KC, pB + (c + 2) * KC, tid);
            CP_COMMIT();
        }

        const uint32_t sA = sb + (uint32_t)(c % 3) * STAGE_B;
        const uint32_t sB = sA + A_BYTES;

        load_frags(fr[0], sA, sB, wm, wn, rloc, khf, 0);
        #pragma unroll
        for (int s = 0; s < 4; ++s) {
            if (s < 3) load_frags(fr[(s + 1) & 1], sA, sB, wm, wn, rloc, khf, s + 1);
            Frag& f = fr[s & 1];
            #pragma unroll
            for (int i = 0; i < 4; ++i)
                #pragma unroll
                for (int j = 0; j < 8; ++j)
                    mma_f16(acc[i][j], f.a[i], f.b[j]);
        }
    }

    // epilogue: c0,c1 at (row, 2*(lane%4)), c2,c3 at (row+8, same cols)
    const int r0 = lane >> 2;
    const int c0 = (lane & 3) << 1;
    float* ob = out + ((size_t)b * TC + m0 + wm + r0) * DD + (n0 + wn + c0);
    #pragma unroll
    for (int i = 0; i < 4; ++i) {
        #pragma unroll
        for (int j = 0; j < 8; ++j) {
            float2 v0 = make_float2(acc[i][j][0], acc[i][j][1]);
            float2 v1 = make_float2(acc[i][j][2], acc[i][j][3]);
            float* p = ob + (size_t)(i * 16) * DD + j * 8;
            *reinterpret_cast<float2*>(p) = v0;
            *reinterpret_cast<float2*>(p + (size_t)8 * DD) = v1;
        }
    }
}

// ---------------------------------------------------------------------------
// Launch
// ---------------------------------------------------------------------------
extern "C" void kernel_launch(void* const* d_in, const int* in_sizes, int n_in,
                              void* d_out, int out_size) {
    (void)in_sizes; (void)n_in; (void)out_size;
    const float* sim = (const float*)d_in[0];   // [8, 2048, 1024]
    const float* q   = (const float*)d_in[1];   // [8, 1024, 1024]
    float* out = (float*)d_out;                 // [8, 2048, 1024]

    softmax_kernel<<<BB * TC / 8, 256>>>(sim);
    transpose_kernel<<<dim3(TQ / 32, DD / 32, BB), dim3(32, 8)>>>(q);

    cudaFuncSetAttribute(gemm_f16_kernel,
                         cudaFuncAttributeMaxDynamicSharedMemorySize, SMEM_TOTAL);
    gemm_f16_kernel<<<dim3(DD / BN, TC / BM, BB), GTHREADS, SMEM_TOTAL>>>(out);
}